// round 2
// baseline (speedup 1.0000x reference)
#include <cuda_runtime.h>
#include <cuda_bf16.h>
#include <cstdint>

// Content-addressed select: out = cached_outputs[idx] where idx = first
// fingerprint row equal to x[0..3], else 0. Pure HBM stream copy:
// 256 MiB read + 256 MiB write.
//
// R2 changes vs R1 (83.6us, 6173 GB/s, DRAM 77.9%):
//  - __stwt write-through stores (avoid L2 write-allocate contention with
//    the read stream)
//  - block-contiguous layout, ITERS=16 (DRAM page locality + higher MLP)

static constexpr long long SLAB_ELEMS = 16384LL * 4096LL;   // 67,108,864 floats
static constexpr long long N4         = SLAB_ELEMS / 4;     // 16,777,216 float4
static constexpr int       N_CASES    = 6;

static constexpr int THREADS = 256;
static constexpr int ITERS   = 16;                           // float4 per thread
static constexpr int BLOCKS  = (int)(N4 / (ITERS * THREADS)); // 4096
static_assert((long long)BLOCKS * ITERS * THREADS == N4, "exact cover");

__device__ __forceinline__ int select_idx(const float* __restrict__ x,
                                          const float* __restrict__ fp) {
    const float p0 = __ldg(&x[0]);
    const float p1 = __ldg(&x[1]);
    const float p2 = __ldg(&x[2]);
    const float p3 = __ldg(&x[3]);
    int idx = 0;
    // Reverse iteration: lowest matching index wins (== argmax of first True);
    // no match leaves idx = 0.
    #pragma unroll
    for (int i = N_CASES - 1; i >= 0; --i) {
        const float f0 = __ldg(&fp[i * 4 + 0]);
        const float f1 = __ldg(&fp[i * 4 + 1]);
        const float f2 = __ldg(&fp[i * 4 + 2]);
        const float f3 = __ldg(&fp[i * 4 + 3]);
        if (f0 == p0 && f1 == p1 && f2 == p2 && f3 == p3) idx = i;
    }
    return idx;
}

__global__ __launch_bounds__(THREADS)
void cache_select_copy_kernel(const float* __restrict__ x,
                              const float* __restrict__ fingerprints,
                              const float4* __restrict__ cached,
                              float4* __restrict__ out) {
    const int idx = select_idx(x, fingerprints);
    const float4* __restrict__ src = cached + (long long)idx * N4;

    // Block-contiguous: each block owns a contiguous ITERS*THREADS*16B = 64 KiB
    // chunk; iterations step by 4 KiB within it (DRAM page friendly).
    const long long base = (long long)blockIdx.x * (ITERS * THREADS) + threadIdx.x;

    #pragma unroll
    for (int it = 0; it < ITERS; ++it) {
        const long long i = base + (long long)it * THREADS;
        float4 v = __ldcs(&src[i]);   // evict-first read stream
        __stwt(&out[i], v);           // write-through: no L2 dirty allocate
    }
}

extern "C" void kernel_launch(void* const* d_in, const int* in_sizes, int n_in,
                              void* d_out, int out_size) {
    const float*  x      = (const float*)d_in[0];
    const float*  fps    = (const float*)d_in[1];
    const float4* cached = (const float4*)d_in[2];
    float4*       out    = (float4*)d_out;

    cache_select_copy_kernel<<<BLOCKS, THREADS>>>(x, fps, cached, out);
}

// round 3
// speedup vs baseline: 1.0376x; 1.0376x over previous
#include <cuda_runtime.h>
#include <cuda_bf16.h>
#include <cstdint>

// Content-addressed select: out = cached_outputs[idx] where idx = first
// fingerprint row equal to x[0..3], else 0. Pure HBM stream copy:
// 256 MiB read + 256 MiB write.
//
// R3: revert R2's __stwt + block-contiguous regression (88.4us, DRAM 73.4%).
// Back to R1's grid-strided __ldcs/__stcs (83.6us, DRAM 77.9%), single change:
// ITERS 8 -> 16 for deeper per-warp MLP / DRAM queue depth.

static constexpr long long SLAB_ELEMS = 16384LL * 4096LL;   // 67,108,864 floats
static constexpr long long N4         = SLAB_ELEMS / 4;     // 16,777,216 float4
static constexpr int       N_CASES    = 6;

static constexpr int THREADS = 256;
static constexpr int ITERS   = 16;                            // float4 per thread
static constexpr int BLOCKS  = (int)(N4 / ((long long)ITERS * THREADS)); // 4096
static_assert((long long)BLOCKS * ITERS * THREADS == N4, "exact cover");

__device__ __forceinline__ int select_idx(const float* __restrict__ x,
                                          const float* __restrict__ fp) {
    // Probe = first 4 floats of x. Broadcast loads — L2 hit for all threads.
    const float p0 = __ldg(&x[0]);
    const float p1 = __ldg(&x[1]);
    const float p2 = __ldg(&x[2]);
    const float p3 = __ldg(&x[3]);
    int idx = 0;
    // Reverse iteration: lowest matching index wins (== argmax of first True);
    // no match leaves idx = 0.
    #pragma unroll
    for (int i = N_CASES - 1; i >= 0; --i) {
        const float f0 = __ldg(&fp[i * 4 + 0]);
        const float f1 = __ldg(&fp[i * 4 + 1]);
        const float f2 = __ldg(&fp[i * 4 + 2]);
        const float f3 = __ldg(&fp[i * 4 + 3]);
        if (f0 == p0 && f1 == p1 && f2 == p2 && f3 == p3) idx = i;
    }
    return idx;
}

__global__ __launch_bounds__(THREADS)
void cache_select_copy_kernel(const float* __restrict__ x,
                              const float* __restrict__ fingerprints,
                              const float4* __restrict__ cached,
                              float4* __restrict__ out) {
    const int idx = select_idx(x, fingerprints);
    const float4* __restrict__ src = cached + (long long)idx * N4;

    // Grid-strided (R1 layout): consecutive threads across the grid cover
    // contiguous 16B chunks; iterations stride by the whole grid.
    const long long tid    = (long long)blockIdx.x * THREADS + threadIdx.x;
    const long long stride = (long long)BLOCKS * THREADS;

    // Fixed trip count -> ptxas front-batches 16 independent LDG.128 (MLP=16).
    #pragma unroll
    for (int it = 0; it < ITERS; ++it) {
        const long long i = tid + (long long)it * stride;
        float4 v = __ldcs(&src[i]);   // evict-first read stream (no reuse)
        __stcs(&out[i], v);           // evict-first write stream
    }
}

extern "C" void kernel_launch(void* const* d_in, const int* in_sizes, int n_in,
                              void* d_out, int out_size) {
    const float*  x      = (const float*)d_in[0];
    const float*  fps    = (const float*)d_in[1];
    const float4* cached = (const float4*)d_in[2];
    float4*       out    = (float4*)d_out;

    cache_select_copy_kernel<<<BLOCKS, THREADS>>>(x, fps, cached, out);
}

// round 4
// speedup vs baseline: 1.0582x; 1.0199x over previous
#include <cuda_runtime.h>
#include <cuda_bf16.h>
#include <cstdint>

// Content-addressed select: out = cached_outputs[idx] where idx = first
// fingerprint row equal to x[0..3], else 0. Pure HBM stream copy:
// 256 MiB read + 256 MiB write. DRAM-roofline bound (~6.8 TB/s aggregate).
//
// R4: single-variable probe around R1 (83.6us, DRAM 77.9%, 8192 blk x ITERS 8):
// ITERS 8 -> 4, BLOCKS 8192 -> 16384. More CTAs for wave balance; per-thread
// MLP=4 still covers DRAM latency at occ ~87%.

static constexpr long long SLAB_ELEMS = 16384LL * 4096LL;   // 67,108,864 floats
static constexpr long long N4         = SLAB_ELEMS / 4;     // 16,777,216 float4
static constexpr int       N_CASES    = 6;

static constexpr int THREADS = 256;
static constexpr int ITERS   = 4;                             // float4 per thread
static constexpr int BLOCKS  = (int)(N4 / ((long long)ITERS * THREADS)); // 16384
static_assert((long long)BLOCKS * ITERS * THREADS == N4, "exact cover");

__device__ __forceinline__ int select_idx(const float* __restrict__ x,
                                          const float* __restrict__ fp) {
    // Probe = first 4 floats of x. Broadcast loads — L2 hit for all threads.
    const float p0 = __ldg(&x[0]);
    const float p1 = __ldg(&x[1]);
    const float p2 = __ldg(&x[2]);
    const float p3 = __ldg(&x[3]);
    int idx = 0;
    // Reverse iteration: lowest matching index wins (== argmax of first True);
    // no match leaves idx = 0.
    #pragma unroll
    for (int i = N_CASES - 1; i >= 0; --i) {
        const float f0 = __ldg(&fp[i * 4 + 0]);
        const float f1 = __ldg(&fp[i * 4 + 1]);
        const float f2 = __ldg(&fp[i * 4 + 2]);
        const float f3 = __ldg(&fp[i * 4 + 3]);
        if (f0 == p0 && f1 == p1 && f2 == p2 && f3 == p3) idx = i;
    }
    return idx;
}

__global__ __launch_bounds__(THREADS)
void cache_select_copy_kernel(const float* __restrict__ x,
                              const float* __restrict__ fingerprints,
                              const float4* __restrict__ cached,
                              float4* __restrict__ out) {
    const int idx = select_idx(x, fingerprints);
    const float4* __restrict__ src = cached + (long long)idx * N4;

    // Grid-strided: consecutive threads across the grid cover contiguous 16B
    // chunks; iterations stride by the whole grid.
    const long long tid    = (long long)blockIdx.x * THREADS + threadIdx.x;
    const long long stride = (long long)BLOCKS * THREADS;

    // Fixed trip count -> ptxas front-batches 4 independent LDG.128.
    #pragma unroll
    for (int it = 0; it < ITERS; ++it) {
        const long long i = tid + (long long)it * stride;
        float4 v = __ldcs(&src[i]);   // evict-first read stream (no reuse)
        __stcs(&out[i], v);           // evict-first write stream
    }
}

extern "C" void kernel_launch(void* const* d_in, const int* in_sizes, int n_in,
                              void* d_out, int out_size) {
    const float*  x      = (const float*)d_in[0];
    const float*  fps    = (const float*)d_in[1];
    const float4* cached = (const float4*)d_in[2];
    float4*       out    = (float4*)d_out;

    cache_select_copy_kernel<<<BLOCKS, THREADS>>>(x, fps, cached, out);
}